// round 5
// baseline (speedup 1.0000x reference)
#include <cuda_runtime.h>

// ---------------------------------------------------------------------------
// FeatureExtractorViT  (B=512, C=3, IMG=36, PS=6, S=36, D=768, H=12, HD=64,
//                       L=4, OUT=256)
// Token count NT = B*C*S = 55296.  All math fp32 (rel_err target 1e-3).
// ---------------------------------------------------------------------------

#define NT    55296      // B*C*S tokens
#define DD    768
#define NBC   1536       // B*C sequences
#define SS    36
#define NH    12
#define HDIM  64
#define NL    4
#define DOUT  256
#define DMLP  1536

// Scratch (device globals — allocation inside kernel_launch is forbidden)
static __device__ float g_z[NT * DD];     // residual stream
static __device__ float g_h[NT * DD];     // layernorm output
static __device__ float g_q[NT * DD];
static __device__ float g_k[NT * DD];
static __device__ float g_v[NT * DD];
static __device__ float g_m[NT * DMLP];   // MLP hidden

// ---------------------------------------------------------------------------
// 1) Patch embed: z[bc,s,d] = sum_p pixel[bc,s,p]*Wp[d,p] + bp[d] + pos[s,d]
//    grid (6, 1536), block 128: each block = 128 d-channels for one sequence.
// ---------------------------------------------------------------------------
__global__ void patch_embed_kernel(const float* __restrict__ batch,
                                   const float* __restrict__ Wp,
                                   const float* __restrict__ bp,
                                   const float* __restrict__ pos)
{
    __shared__ float px[36 * 36];     // [s][p]
    __shared__ float Ws[128 * 36];    // [d_local][p]
    const int bc = blockIdx.y;
    const int d0 = blockIdx.x * 128;
    const int t  = threadIdx.x;

    const float* img = batch + bc * 1296;
    for (int e = t; e < 1296; e += 128) {
        int row = e / 36, col = e - row * 36;
        int s = (row / 6) * 6 + (col / 6);
        int p = (row % 6) * 6 + (col % 6);
        px[s * 36 + p] = img[e];
    }
    for (int i = t; i < 128 * 36; i += 128)
        Ws[i] = Wp[d0 * 36 + i];
    __syncthreads();

    const int d = d0 + t;
    float w[36];
#pragma unroll
    for (int p = 0; p < 36; p++) w[p] = Ws[t * 36 + p];
    const float bias = bp[d];

    for (int s = 0; s < 36; s++) {
        float acc = bias + pos[s * 768 + d];
        const float* pr = &px[s * 36];
#pragma unroll
        for (int p = 0; p < 36; p++) acc = fmaf(pr[p], w[p], acc);
        g_z[(bc * 36 + s) * 768 + d] = acc;
    }
}

// ---------------------------------------------------------------------------
// 2) LayerNorm: one block (256 threads) per token row of 768.
// ---------------------------------------------------------------------------
__global__ void ln_kernel(const float* __restrict__ in, float* __restrict__ out,
                          const float* __restrict__ gamma,
                          const float* __restrict__ beta)
{
    const int row = blockIdx.x;
    const float* x = in + (size_t)row * 768;
    const int t = threadIdx.x;
    float v0 = x[t], v1 = x[t + 256], v2 = x[t + 512];
    float s = v0 + v1 + v2;
    float q = v0 * v0 + v1 * v1 + v2 * v2;
#pragma unroll
    for (int o = 16; o > 0; o >>= 1) {
        s += __shfl_xor_sync(0xffffffffu, s, o);
        q += __shfl_xor_sync(0xffffffffu, q, o);
    }
    __shared__ float rs[8], rq[8];
    __shared__ float smean, srstd;
    if ((t & 31) == 0) { rs[t >> 5] = s; rq[t >> 5] = q; }
    __syncthreads();
    if (t == 0) {
        float S = 0.f, Q = 0.f;
#pragma unroll
        for (int i = 0; i < 8; i++) { S += rs[i]; Q += rq[i]; }
        float m   = S * (1.0f / 768.0f);
        float var = Q * (1.0f / 768.0f) - m * m;
        smean = m;
        srstd = rsqrtf(var + 1e-5f);
    }
    __syncthreads();
    const float m = smean, r = srstd;
    float* o = out + (size_t)row * 768;
    o[t]       = (v0 - m) * r * gamma[t]       + beta[t];
    o[t + 256] = (v1 - m) * r * gamma[t + 256] + beta[t + 256];
    o[t + 512] = (v2 - m) * r * gamma[t + 512] + beta[t + 512];
}

// ---------------------------------------------------------------------------
// 3) Per-head QKV: q[tok,h,e] = sum_d h[tok,h,d]*Wq[h,e,d] + bq[h,e]
//    grid (NT/64, 12), block 256: 64-token x 64-e tile, loop over {q,k,v}.
// ---------------------------------------------------------------------------
__global__ void __launch_bounds__(256)
qkv_kernel(const float* __restrict__ Wq, const float* __restrict__ bq,
           const float* __restrict__ Wk, const float* __restrict__ bk,
           const float* __restrict__ Wv, const float* __restrict__ bv)
{
    __shared__ float Hs[64 * 65];   // [tok][d], padded
    __shared__ float Ws[64 * 65];   // [d][e],   padded
    __shared__ float bs[64];
    const int m0 = blockIdx.x * 64;
    const int h  = blockIdx.y;
    const int t  = threadIdx.x;

    for (int idx = t; idx < 4096; idx += 256) {
        int tok = idx >> 6, e = idx & 63;
        Hs[tok * 65 + e] = g_h[(size_t)(m0 + tok) * 768 + h * 64 + e];
    }
    const float* Wlist[3] = { Wq + h * 4096, Wk + h * 4096, Wv + h * 4096 };
    const float* blist[3] = { bq + h * 64,   bk + h * 64,   bv + h * 64 };
    float* olist[3] = { g_q, g_k, g_v };
    const int tx = t & 15, ty = t >> 4;

#pragma unroll
    for (int w = 0; w < 3; w++) {
        __syncthreads();   // previous compute done before overwriting Ws
        const float* W = Wlist[w];
        for (int idx = t; idx < 4096; idx += 256) {
            int e = idx >> 6, d = idx & 63;
            Ws[d * 65 + e] = W[idx];
        }
        if (t < 64) bs[t] = blist[w][t];
        __syncthreads();

        float acc[4][4] = {};
        for (int d = 0; d < 64; d++) {
            float a[4], b[4];
#pragma unroll
            for (int i = 0; i < 4; i++) a[i] = Hs[(ty * 4 + i) * 65 + d];
#pragma unroll
            for (int j = 0; j < 4; j++) b[j] = Ws[d * 65 + tx * 4 + j];
#pragma unroll
            for (int i = 0; i < 4; i++)
#pragma unroll
                for (int j = 0; j < 4; j++)
                    acc[i][j] = fmaf(a[i], b[j], acc[i][j]);
        }
        float* o = olist[w];
#pragma unroll
        for (int i = 0; i < 4; i++)
#pragma unroll
            for (int j = 0; j < 4; j++)
                o[(size_t)(m0 + ty * 4 + i) * 768 + h * 64 + tx * 4 + j] =
                    acc[i][j] + bs[tx * 4 + j];
    }
}

// ---------------------------------------------------------------------------
// 4) Attention per (sequence, head): 36x36 scores, softmax, @V, residual add.
//    grid (1536, 12), block 256.
// ---------------------------------------------------------------------------
__global__ void __launch_bounds__(256) attn_kernel()
{
    __shared__ float Qs[36 * 65], Ks[36 * 65], Vs[36 * 65];
    __shared__ float P[36 * 40];
    const int bc = blockIdx.x, h = blockIdx.y;
    const int t = threadIdx.x;
    const size_t base = (size_t)bc * 36 * 768 + h * 64;

    for (int idx = t; idx < 2304; idx += 256) {
        int s_ = idx >> 6, e = idx & 63;
        size_t gi = base + (size_t)s_ * 768 + e;
        Qs[s_ * 65 + e] = g_q[gi];
        Ks[s_ * 65 + e] = g_k[gi];
        Vs[s_ * 65 + e] = g_v[gi];
    }
    __syncthreads();

    for (int sc = t; sc < 1296; sc += 256) {
        int i = sc / 36, j = sc - i * 36;
        float a = 0.f;
        const float* qi = &Qs[i * 65];
        const float* kj = &Ks[j * 65];
#pragma unroll
        for (int e = 0; e < 64; e++) a = fmaf(qi[e], kj[e], a);
        P[i * 40 + j] = a * 0.125f;   // 1/sqrt(64)
    }
    __syncthreads();

    if (t < 36) {
        float mx = -1e30f;
        for (int j = 0; j < 36; j++) mx = fmaxf(mx, P[t * 40 + j]);
        float sum = 0.f;
        for (int j = 0; j < 36; j++) {
            float ex = expf(P[t * 40 + j] - mx);
            P[t * 40 + j] = ex;
            sum += ex;
        }
        float inv = 1.f / sum;
        for (int j = 0; j < 36; j++) P[t * 40 + j] *= inv;
    }
    __syncthreads();

    for (int oi = t; oi < 2304; oi += 256) {
        int i = oi >> 6, e = oi & 63;
        float acc = 0.f;
        const float* pi = &P[i * 40];
#pragma unroll
        for (int j = 0; j < 36; j++) acc = fmaf(pi[j], Vs[j * 65 + e], acc);
        g_z[base + (size_t)i * 768 + e] += acc;   // residual, unique per (bc,h,e)
    }
}

// ---------------------------------------------------------------------------
// 5) SGEMM: C[M,N] = A[M,K] @ B[N,K]^T + bias[N]  (+ReLU) (+res[M,N])
//    128x128 tile, BK=8, 256 threads, 8x8 microtile, register prefetch.
// ---------------------------------------------------------------------------
template <bool RELU, bool RES>
__global__ void __launch_bounds__(256)
sgemm_tn(const float* __restrict__ A, const float* __restrict__ B,
         const float* __restrict__ bias, const float* __restrict__ res,
         float* __restrict__ C, int M, int N, int K)
{
    __shared__ float As[8][128];
    __shared__ float Bs[8][128];
    const int t  = threadIdx.x;
    const int n0 = blockIdx.x * 128;
    const int m0 = blockIdx.y * 128;
    const int lr = t >> 1;            // tile row 0..127
    const int lc = (t & 1) * 4;       // k offset 0 / 4
    const float* Aptr = A + (size_t)(m0 + lr) * K + lc;
    const float* Bptr = B + (size_t)(n0 + lr) * K + lc;
    const int tx = t & 15, ty = t >> 4;

    float acc[8][8] = {};
    float4 ra = *(const float4*)Aptr;
    float4 rb = *(const float4*)Bptr;
    const int NK = K >> 3;

    for (int ks = 0; ks < NK; ks++) {
        As[lc + 0][lr] = ra.x; As[lc + 1][lr] = ra.y;
        As[lc + 2][lr] = ra.z; As[lc + 3][lr] = ra.w;
        Bs[lc + 0][lr] = rb.x; Bs[lc + 1][lr] = rb.y;
        Bs[lc + 2][lr] = rb.z; Bs[lc + 3][lr] = rb.w;
        __syncthreads();
        if (ks + 1 < NK) {             // prefetch next tile into registers
            ra = *(const float4*)(Aptr + (ks + 1) * 8);
            rb = *(const float4*)(Bptr + (ks + 1) * 8);
        }
#pragma unroll
        for (int k = 0; k < 8; k++) {
            float a[8], b[8];
            *(float4*)&a[0] = *(const float4*)&As[k][ty * 8];
            *(float4*)&a[4] = *(const float4*)&As[k][ty * 8 + 4];
            *(float4*)&b[0] = *(const float4*)&Bs[k][tx * 8];
            *(float4*)&b[4] = *(const float4*)&Bs[k][tx * 8 + 4];
#pragma unroll
            for (int i = 0; i < 8; i++)
#pragma unroll
                for (int j = 0; j < 8; j++)
                    acc[i][j] = fmaf(a[i], b[j], acc[i][j]);
        }
        __syncthreads();
    }

    float bv[8];
    *(float4*)&bv[0] = *(const float4*)&bias[n0 + tx * 8];
    *(float4*)&bv[4] = *(const float4*)&bias[n0 + tx * 8 + 4];
#pragma unroll
    for (int i = 0; i < 8; i++) {
        const int row = m0 + ty * 8 + i;
        const size_t off = (size_t)row * N + n0 + tx * 8;
        float v[8];
#pragma unroll
        for (int j = 0; j < 8; j++) {
            float x = acc[i][j] + bv[j];
            if (RELU) x = fmaxf(x, 0.f);
            v[j] = x;
        }
        if (RES) {
            float4 r0 = *(const float4*)&res[off];
            float4 r1 = *(const float4*)&res[off + 4];
            v[0] += r0.x; v[1] += r0.y; v[2] += r0.z; v[3] += r0.w;
            v[4] += r1.x; v[5] += r1.y; v[6] += r1.z; v[7] += r1.w;
        }
        *(float4*)&C[off]     = make_float4(v[0], v[1], v[2], v[3]);
        *(float4*)&C[off + 4] = make_float4(v[4], v[5], v[6], v[7]);
    }
}

// ---------------------------------------------------------------------------
// Launch
// ---------------------------------------------------------------------------
extern "C" void kernel_launch(void* const* d_in, const int* in_sizes, int n_in,
                              void* d_out, int out_size)
{
    (void)in_sizes; (void)n_in; (void)out_size;
    const float* batch = (const float*)d_in[0];
    const float* Wp    = (const float*)d_in[1];
    const float* bp    = (const float*)d_in[2];
    const float* pos   = (const float*)d_in[3];
    const float* ln1g  = (const float*)d_in[4];
    const float* ln1b  = (const float*)d_in[5];
    const float* Wq    = (const float*)d_in[6];
    const float* bq    = (const float*)d_in[7];
    const float* Wk    = (const float*)d_in[8];
    const float* bk    = (const float*)d_in[9];
    const float* Wv    = (const float*)d_in[10];
    const float* bv    = (const float*)d_in[11];
    const float* ln2g  = (const float*)d_in[12];
    const float* ln2b  = (const float*)d_in[13];
    const float* W1    = (const float*)d_in[14];
    const float* b1    = (const float*)d_in[15];
    const float* W2    = (const float*)d_in[16];
    const float* b2    = (const float*)d_in[17];
    const float* Wout  = (const float*)d_in[18];
    const float* bout  = (const float*)d_in[19];

    float *zp = nullptr, *hp = nullptr, *mp = nullptr;
    cudaGetSymbolAddress((void**)&zp, g_z);
    cudaGetSymbolAddress((void**)&hp, g_h);
    cudaGetSymbolAddress((void**)&mp, g_m);

    patch_embed_kernel<<<dim3(6, NBC), 128>>>(batch, Wp, bp, pos);

    for (int l = 0; l < NL; l++) {
        ln_kernel<<<NT, 256>>>(zp, hp, ln1g + l * 768, ln1b + l * 768);
        qkv_kernel<<<dim3(NT / 64, NH), 256>>>(
            Wq + l * NH * 4096, bq + l * NH * 64,
            Wk + l * NH * 4096, bk + l * NH * 64,
            Wv + l * NH * 4096, bv + l * NH * 64);
        attn_kernel<<<dim3(NBC, NH), 256>>>();
        ln_kernel<<<NT, 256>>>(zp, hp, ln2g + l * 768, ln2b + l * 768);
        sgemm_tn<true,  false><<<dim3(DMLP / 128, NT / 128), 256>>>(
            hp, W1 + (size_t)l * DMLP * DD, b1 + l * DMLP, nullptr, mp,
            NT, DMLP, DD);
        sgemm_tn<false, true><<<dim3(DD / 128, NT / 128), 256>>>(
            mp, W2 + (size_t)l * DD * DMLP, b2 + l * DD, hp, zp,
            NT, DD, DMLP);
    }

    sgemm_tn<false, false><<<dim3(DOUT / 128, NT / 128), 256>>>(
        zp, Wout, bout, nullptr, (float*)d_out, NT, DOUT, DD);
}